// round 12
// baseline (speedup 1.0000x reference)
#include <cuda_runtime.h>
#include <cuda_bf16.h>

// Problem: B=2, L=2048, D=1024, H=16, DH=64
// Output buffer: [output (B,L,D) = 4,194,304 f32][attn (B,H,L,L) = 134,217,728 f32]

#define B_SZ   2
#define L_SZ   2048
#define D_SZ   1024
#define H_SZ   16
#define DH_SZ  64

static constexpr size_t OUT_ELEMS  = (size_t)B_SZ * L_SZ * D_SZ;        // 4194304
static constexpr size_t ATTN_ELEMS = (size_t)B_SZ * H_SZ * L_SZ * L_SZ; // 134217728
static constexpr size_t QKV_ELEMS  = (size_t)B_SZ * H_SZ * L_SZ * DH_SZ;// 4194304

// Scratch (allocation-free rule: __device__ globals)
__device__ __align__(16) float g_q[QKV_ELEMS];   // reused as ctx concat (B,L,D) after AV
__device__ __align__(16) float g_k[QKV_ELEMS];
__device__ __align__(16) float g_v[QKV_ELEMS];
__device__ __align__(16) float2 g_stats[(size_t)B_SZ * H_SZ * L_SZ];  // {rowmax, 1/Z}
// Fallback attn scratch in case out_size only covers `output`
__device__ __align__(16) float g_attn_fb[ATTN_ELEMS];

__device__ __forceinline__ unsigned f2tf(float f) {
    unsigned u;
    asm("cvt.rna.tf32.f32 %0, %1;" : "=r"(u) : "f"(f));
    return u;
}

__device__ __forceinline__ void mma8(float c[4], const unsigned a[4], const unsigned b[2]) {
    asm volatile(
        "mma.sync.aligned.m16n8k8.row.col.f32.tf32.tf32.f32 "
        "{%0,%1,%2,%3}, {%4,%5,%6,%7}, {%8,%9}, {%0,%1,%2,%3};"
        : "+f"(c[0]), "+f"(c[1]), "+f"(c[2]), "+f"(c[3])
        : "r"(a[0]), "r"(a[1]), "r"(a[2]), "r"(a[3]), "r"(b[0]), "r"(b[1]));
}

// merge two (max, sumexp) pairs
__device__ __forceinline__ void mz_merge(float& m, float& z, float om, float oz) {
    float mn = fmaxf(m, om);
    z = z * __expf(m - mn) + oz * __expf(om - mn);
    m = mn;
}

// ============================================================================
// NT GEMM: C[M=4096, N=1024] = A[4096,1024] * W[1024,1024]^T, TF32 mma.
// 512 threads, 16 warps (4m x 4n), warp tile 32x32, BM=BN=128, BK=32.
// 2-stage smem double buffer with register prefetch.
// mode < 0: md = blockIdx.z in {0,1,2}: A = x, scatter into g_q/g_k/g_v (B,H,L,DH).
// mode == 3: A = g_q (ctx concat), plain row-major write to dst.
// ============================================================================
static constexpr int PROJ_SMEM = (2 * 128 * 36 * 2) * 4;  // 73728 B

__global__ void __launch_bounds__(512) proj_kernel(
    const float* __restrict__ Ain, const float* __restrict__ W0,
    const float* __restrict__ W1, const float* __restrict__ W2,
    float* __restrict__ dst, int mode)
{
    extern __shared__ unsigned sh[];
    unsigned (*As)[128][36] = (unsigned(*)[128][36])sh;
    unsigned (*Ws)[128][36] = (unsigned(*)[128][36])(sh + 2 * 128 * 36);

    const int md = (mode < 0) ? (int)blockIdx.z : mode;
    const float* W = (md == 1) ? W1 : (md == 2) ? W2 : W0;
    const float* A = (md == 3) ? (const float*)g_q : Ain;

    const int tid  = threadIdx.x;
    const int wid  = tid >> 5;
    const int lane = tid & 31;
    const int g = lane >> 2, t = lane & 3;
    const int warp_m = wid & 3, warp_n = wid >> 2;
    const int m0 = blockIdx.y * 128;
    const int n0 = blockIdx.x * 128;

    const int lr = tid >> 3;          // 0..63 (row within stage, +64 for i=1)
    const int lc = (tid & 7) << 2;    // 0..28

    float acc[2][4][4];
#pragma unroll
    for (int i = 0; i < 2; i++)
#pragma unroll
        for (int j = 0; j < 4; j++)
#pragma unroll
            for (int c = 0; c < 4; c++) acc[i][j][c] = 0.f;

    // preload stage 0
#pragma unroll
    for (int i = 0; i < 2; i++) {
        int r = lr + i * 64;
        float4 fa = *(const float4*)(A + (size_t)(m0 + r) * 1024 + lc);
        float4 fw = *(const float4*)(W + (size_t)(n0 + r) * 1024 + lc);
        *(uint4*)&As[0][r][lc] = make_uint4(f2tf(fa.x), f2tf(fa.y), f2tf(fa.z), f2tf(fa.w));
        *(uint4*)&Ws[0][r][lc] = make_uint4(f2tf(fw.x), f2tf(fw.y), f2tf(fw.z), f2tf(fw.w));
    }
    __syncthreads();

    int st = 0;
    for (int k0 = 0; k0 < 1024; k0 += 32) {
        const bool nxt = (k0 + 32) < 1024;
        float4 pa[2], pw[2];
        if (nxt) {
#pragma unroll
            for (int i = 0; i < 2; i++) {
                int r = lr + i * 64;
                pa[i] = *(const float4*)(A + (size_t)(m0 + r) * 1024 + k0 + 32 + lc);
                pw[i] = *(const float4*)(W + (size_t)(n0 + r) * 1024 + k0 + 32 + lc);
            }
        }
#pragma unroll
        for (int kk = 0; kk < 32; kk += 8) {
            unsigned af[2][4], bf[4][2];
#pragma unroll
            for (int i = 0; i < 2; i++) {
                int rb = warp_m * 32 + i * 16 + g;
                af[i][0] = As[st][rb][kk + t];
                af[i][1] = As[st][rb + 8][kk + t];
                af[i][2] = As[st][rb][kk + t + 4];
                af[i][3] = As[st][rb + 8][kk + t + 4];
            }
#pragma unroll
            for (int j = 0; j < 4; j++) {
                int cb = warp_n * 32 + j * 8 + g;
                bf[j][0] = Ws[st][cb][kk + t];
                bf[j][1] = Ws[st][cb][kk + t + 4];
            }
#pragma unroll
            for (int i = 0; i < 2; i++)
#pragma unroll
                for (int j = 0; j < 4; j++)
                    mma8(acc[i][j], af[i], bf[j]);
        }
        if (nxt) {
#pragma unroll
            for (int i = 0; i < 2; i++) {
                int r = lr + i * 64;
                *(uint4*)&As[st ^ 1][r][lc] = make_uint4(f2tf(pa[i].x), f2tf(pa[i].y), f2tf(pa[i].z), f2tf(pa[i].w));
                *(uint4*)&Ws[st ^ 1][r][lc] = make_uint4(f2tf(pw[i].x), f2tf(pw[i].y), f2tf(pw[i].z), f2tf(pw[i].w));
            }
        }
        __syncthreads();
        st ^= 1;
    }

    // Epilogue
#pragma unroll
    for (int i = 0; i < 2; i++) {
#pragma unroll
        for (int j = 0; j < 4; j++) {
            int r0 = m0 + warp_m * 32 + i * 16 + g;
            int c0 = n0 + warp_n * 32 + j * 8 + 2 * t;
            float2 lo = make_float2(acc[i][j][0], acc[i][j][1]);
            float2 hi = make_float2(acc[i][j][2], acc[i][j][3]);
            if (md == 3) {
                *(float2*)(dst + (size_t)r0 * 1024 + c0) = lo;
                *(float2*)(dst + (size_t)(r0 + 8) * 1024 + c0) = hi;
            } else {
                float* qkv = (md == 0) ? g_q : (md == 1) ? g_k : g_v;
                size_t i0 = ((size_t)((r0 >> 11) * H_SZ + (c0 >> 6)) * L_SZ + (r0 & 2047)) * DH_SZ + (c0 & 63);
                *(float2*)(qkv + i0) = lo;
                int r1 = r0 + 8;
                size_t i1 = ((size_t)((r1 >> 11) * H_SZ + (c0 >> 6)) * L_SZ + (r1 & 2047)) * DH_SZ + (c0 & 63);
                *(float2*)(qkv + i1) = hi;
            }
        }
    }
}

// ============================================================================
// Stats (flash pass-1): per (b,h, row-block 128), recompute S = Q K^T * 0.125
// streaming K in 128-col tiles; produce per-row (max M, 1/Z), Z = sum exp(s-M).
// Same mma fragment order as the scores kernel -> bit-identical s values.
// ============================================================================
static constexpr int STAT_SMEM = (128 * 68 + 2 * 128 * 68 + 4 * 128 * 2) * 4; // 108544 B

__global__ void __launch_bounds__(512) stats_kernel()
{
    extern __shared__ unsigned sh[];
    unsigned (*Qs)[68]       = (unsigned(*)[68])sh;
    unsigned (*Ks)[128][68]  = (unsigned(*)[128][68])(sh + 128 * 68);
    float    (*red)[128][2]  = (float(*)[128][2])(sh + 128 * 68 + 2 * 128 * 68);

    const int tid  = threadIdx.x;
    const int wid  = tid >> 5;
    const int lane = tid & 31;
    const int g = lane >> 2, t = lane & 3;
    const int warp_m = wid & 3, warp_n = wid >> 2;
    const int m0 = blockIdx.x * 128;
    const int bh = blockIdx.y;

    const float* Qb = g_q + (size_t)bh * L_SZ * DH_SZ;
    const float* Kb = g_k + (size_t)bh * L_SZ * DH_SZ;

    const int lr = tid >> 4;          // 0..31 (+32 per i), 16 float4 per 64-wide row
    const int lc = (tid & 15) << 2;

    // Load Q tile (128x64) once, and K tile 0
#pragma unroll
    for (int i = 0; i < 4; i++) {
        int r = lr + i * 32;
        float4 fq = *(const float4*)(Qb + (size_t)(m0 + r) * DH_SZ + lc);
        *(uint4*)&Qs[r][lc] = make_uint4(f2tf(fq.x), f2tf(fq.y), f2tf(fq.z), f2tf(fq.w));
        float4 fk = *(const float4*)(Kb + (size_t)r * DH_SZ + lc);
        *(uint4*)&Ks[0][r][lc] = make_uint4(f2tf(fk.x), f2tf(fk.y), f2tf(fk.z), f2tf(fk.w));
    }
    __syncthreads();

    float m_[4] = {-1e30f, -1e30f, -1e30f, -1e30f};
    float z_[4] = {0.f, 0.f, 0.f, 0.f};

    int st = 0;
    for (int n0 = 0; n0 < L_SZ; n0 += 128) {
        const bool nxt = (n0 + 128) < L_SZ;
        float4 pk[4];
        if (nxt) {
#pragma unroll
            for (int i = 0; i < 4; i++) {
                int r = lr + i * 32;
                pk[i] = *(const float4*)(Kb + (size_t)(n0 + 128 + r) * DH_SZ + lc);
            }
        }
        float acc[2][4][4];
#pragma unroll
        for (int i = 0; i < 2; i++)
#pragma unroll
            for (int j = 0; j < 4; j++)
#pragma unroll
                for (int c = 0; c < 4; c++) acc[i][j][c] = 0.f;

#pragma unroll
        for (int kk = 0; kk < 64; kk += 8) {
            unsigned af[2][4], bf[4][2];
#pragma unroll
            for (int i = 0; i < 2; i++) {
                int rb = warp_m * 32 + i * 16 + g;
                af[i][0] = Qs[rb][kk + t];
                af[i][1] = Qs[rb + 8][kk + t];
                af[i][2] = Qs[rb][kk + t + 4];
                af[i][3] = Qs[rb + 8][kk + t + 4];
            }
#pragma unroll
            for (int j = 0; j < 4; j++) {
                int cb = warp_n * 32 + j * 8 + g;
                bf[j][0] = Ks[st][cb][kk + t];
                bf[j][1] = Ks[st][cb][kk + t + 4];
            }
#pragma unroll
            for (int i = 0; i < 2; i++)
#pragma unroll
                for (int j = 0; j < 4; j++)
                    mma8(acc[i][j], af[i], bf[j]);
        }
        if (nxt) {
#pragma unroll
            for (int i = 0; i < 4; i++) {
                int r = lr + i * 32;
                *(uint4*)&Ks[st ^ 1][r][lc] = make_uint4(f2tf(pk[i].x), f2tf(pk[i].y), f2tf(pk[i].z), f2tf(pk[i].w));
            }
        }
        // online (m,z) update from this tile (register-only)
#pragma unroll
        for (int i = 0; i < 2; i++) {
#pragma unroll
            for (int half = 0; half < 2; half++) {
                int ri = i * 2 + half;
                float v[8];
#pragma unroll
                for (int j = 0; j < 4; j++) {
                    v[2 * j]     = acc[i][j][half * 2]     * 0.125f;
                    v[2 * j + 1] = acc[i][j][half * 2 + 1] * 0.125f;
                }
                float tm = v[0];
#pragma unroll
                for (int k = 1; k < 8; k++) tm = fmaxf(tm, v[k]);
                float mn = fmaxf(m_[ri], tm);
                float zs = 0.f;
#pragma unroll
                for (int k = 0; k < 8; k++) zs += __expf(v[k] - mn);
                z_[ri] = z_[ri] * __expf(m_[ri] - mn) + zs;
                m_[ri] = mn;
            }
        }
        __syncthreads();
        st ^= 1;
    }

    // combine across the 4 t-lanes sharing the same rows
#pragma unroll
    for (int ri = 0; ri < 4; ri++) {
#pragma unroll
        for (int o = 1; o < 4; o <<= 1) {
            float om = __shfl_xor_sync(0xffffffffu, m_[ri], o);
            float oz = __shfl_xor_sync(0xffffffffu, z_[ri], o);
            mz_merge(m_[ri], z_[ri], om, oz);
        }
    }
    if (t == 0) {
#pragma unroll
        for (int i = 0; i < 2; i++) {
            int rl = warp_m * 32 + i * 16 + g;
            red[warp_n][rl][0]     = m_[i * 2];
            red[warp_n][rl][1]     = z_[i * 2];
            red[warp_n][rl + 8][0] = m_[i * 2 + 1];
            red[warp_n][rl + 8][1] = z_[i * 2 + 1];
        }
    }
    __syncthreads();
    if (tid < 128) {
        float M = red[0][tid][0], Z = red[0][tid][1];
#pragma unroll
        for (int w = 1; w < 4; w++) mz_merge(M, Z, red[w][tid][0], red[w][tid][1]);
        g_stats[(size_t)bh * L_SZ + m0 + tid] = make_float2(M, 1.0f / Z);
    }
}

// ============================================================================
// Scores + normalize: per (b,h), attn = exp(QK^T * 0.125 - M) * invZ (final!)
// BM=BN=128, K=64 all-in-smem. 512 threads, warps 4x4, tile 32x32.
// ============================================================================
static constexpr int SC_SMEM = (2 * 128 * 68 + 2 * 128) * 4; // 70656 B

__global__ void __launch_bounds__(512) scores_kernel(float* __restrict__ out, int fb)
{
    extern __shared__ unsigned sh[];
    unsigned (*Qs)[68] = (unsigned(*)[68])sh;
    unsigned (*Ks)[68] = (unsigned(*)[68])(sh + 128 * 68);
    float* sM = (float*)(sh + 2 * 128 * 68);
    float* sI = sM + 128;

    float* attn = fb ? g_attn_fb : out + OUT_ELEMS;
    const int bh = blockIdx.z;
    const float* Qb = g_q + (size_t)bh * L_SZ * DH_SZ;
    const float* Kb = g_k + (size_t)bh * L_SZ * DH_SZ;

    const int tid  = threadIdx.x;
    const int wid  = tid >> 5;
    const int lane = tid & 31;
    const int g = lane >> 2, t = lane & 3;
    const int warp_m = wid & 3, warp_n = wid >> 2;
    const int m0 = blockIdx.y * 128;
    const int n0 = blockIdx.x * 128;

    const int lr = tid >> 4;
    const int lc = (tid & 15) << 2;

    if (tid < 128) {
        float2 s = g_stats[(size_t)bh * L_SZ + m0 + tid];
        sM[tid] = s.x; sI[tid] = s.y;
    }
#pragma unroll
    for (int i = 0; i < 4; i++) {
        int r = lr + i * 32;
        float4 fq = *(const float4*)(Qb + (size_t)(m0 + r) * DH_SZ + lc);
        *(uint4*)&Qs[r][lc] = make_uint4(f2tf(fq.x), f2tf(fq.y), f2tf(fq.z), f2tf(fq.w));
        float4 fk = *(const float4*)(Kb + (size_t)(n0 + r) * DH_SZ + lc);
        *(uint4*)&Ks[r][lc] = make_uint4(f2tf(fk.x), f2tf(fk.y), f2tf(fk.z), f2tf(fk.w));
    }
    __syncthreads();

    float acc[2][4][4];
#pragma unroll
    for (int i = 0; i < 2; i++)
#pragma unroll
        for (int j = 0; j < 4; j++)
#pragma unroll
            for (int c = 0; c < 4; c++) acc[i][j][c] = 0.f;

#pragma unroll
    for (int kk = 0; kk < 64; kk += 8) {
        unsigned af[2][4], bf[4][2];
#pragma unroll
        for (int i = 0; i < 2; i++) {
            int rb = warp_m * 32 + i * 16 + g;
            af[i][0] = Qs[rb][kk + t];
            af[i][1] = Qs[rb + 8][kk + t];
            af[i][2] = Qs[rb][kk + t + 4];
            af[i][3] = Qs[rb + 8][kk + t + 4];
        }
#pragma unroll
        for (int j = 0; j < 4; j++) {
            int cb = warp_n * 32 + j * 8 + g;
            bf[j][0] = Ks[cb][kk + t];
            bf[j][1] = Ks[cb][kk + t + 4];
        }
#pragma unroll
        for (int i = 0; i < 2; i++)
#pragma unroll
            for (int j = 0; j < 4; j++)
                mma8(acc[i][j], af[i], bf[j]);
    }

    float* Sb = attn + (size_t)bh * L_SZ * L_SZ;
#pragma unroll
    for (int i = 0; i < 2; i++) {
        int rl = warp_m * 32 + i * 16 + g;
        float M0 = sM[rl],     I0 = sI[rl];
        float M1 = sM[rl + 8], I1 = sI[rl + 8];
#pragma unroll
        for (int j = 0; j < 4; j++) {
            int r0 = m0 + rl;
            int c0 = n0 + warp_n * 32 + j * 8 + 2 * t;
            float2 lo = make_float2(__expf(acc[i][j][0] * 0.125f - M0) * I0,
                                    __expf(acc[i][j][1] * 0.125f - M0) * I0);
            float2 hi = make_float2(__expf(acc[i][j][2] * 0.125f - M1) * I1,
                                    __expf(acc[i][j][3] * 0.125f - M1) * I1);
            *(float2*)(Sb + (size_t)r0 * L_SZ + c0) = lo;
            *(float2*)(Sb + (size_t)(r0 + 8) * L_SZ + c0) = hi;
        }
    }
}

// ============================================================================
// AV: per (b,h), ctx[2048,64] = P[2048,2048] * V[2048,64]
// 512 threads, warps 4(m) x 4(n), warp tile 32x16, BK=32, double-buffered.
// Epilogue writes concat layout (B,L,D) into g_q.
// ============================================================================
static constexpr int AV_SMEM = (2 * 128 * 36 + 2 * 32 * 68) * 4; // 54272 B

__global__ void __launch_bounds__(512) av_kernel(float* __restrict__ out, int fb)
{
    extern __shared__ unsigned sh[];
    unsigned (*Ps)[128][36] = (unsigned(*)[128][36])sh;
    unsigned (*Vs)[32][68]  = (unsigned(*)[32][68])(sh + 2 * 128 * 36);

    float* attn = fb ? g_attn_fb : out + OUT_ELEMS;
    const int bh = blockIdx.y;
    const int m0 = blockIdx.x * 128;
    const int b  = bh >> 4;
    const int h  = bh & 15;

    const int tid  = threadIdx.x;
    const int wid  = tid >> 5;
    const int lane = tid & 31;
    const int g = lane >> 2, t = lane & 3;
    const int warp_m = wid & 3, warp_n = wid >> 2;

    const float* Pb = attn + (size_t)bh * L_SZ * L_SZ + (size_t)m0 * L_SZ;
    const float* Vb = g_v + (size_t)bh * L_SZ * DH_SZ;

    const int pr = tid >> 3;          // P: 0..63 (+64), 8 float4 per 32-wide row
    const int pc = (tid & 7) << 2;
    const int vr = tid >> 4;          // V: 0..31, 16 float4 per 64-wide row
    const int vc = (tid & 15) << 2;

    float acc[2][2][4];
#pragma unroll
    for (int i = 0; i < 2; i++)
#pragma unroll
        for (int j = 0; j < 2; j++)
#pragma unroll
            for (int c = 0; c < 4; c++) acc[i][j][c] = 0.f;

    // preload stage 0
#pragma unroll
    for (int i = 0; i < 2; i++) {
        int r = pr + i * 64;
        float4 f = *(const float4*)(Pb + (size_t)r * L_SZ + pc);
        *(uint4*)&Ps[0][r][pc] = make_uint4(f2tf(f.x), f2tf(f.y), f2tf(f.z), f2tf(f.w));
    }
    {
        float4 f = *(const float4*)(Vb + (size_t)vr * DH_SZ + vc);
        *(uint4*)&Vs[0][vr][vc] = make_uint4(f2tf(f.x), f2tf(f.y), f2tf(f.z), f2tf(f.w));
    }
    __syncthreads();

    int st = 0;
    for (int k0 = 0; k0 < L_SZ; k0 += 32) {
        const bool nxt = (k0 + 32) < L_SZ;
        float4 pp[2], pv;
        if (nxt) {
#pragma unroll
            for (int i = 0; i < 2; i++) {
                int r = pr + i * 64;
                pp[i] = *(const float4*)(Pb + (size_t)r * L_SZ + k0 + 32 + pc);
            }
            pv = *(const float4*)(Vb + (size_t)(k0 + 32 + vr) * DH_SZ + vc);
        }
#pragma unroll
        for (int kk = 0; kk < 32; kk += 8) {
            unsigned af[2][4], bf[2][2];
#pragma unroll
            for (int i = 0; i < 2; i++) {
                int rb = warp_m * 32 + i * 16 + g;
                af[i][0] = Ps[st][rb][kk + t];
                af[i][1] = Ps[st][rb + 8][kk + t];
                af[i][2] = Ps[st][rb][kk + t + 4];
                af[i][3] = Ps[st][rb + 8][kk + t + 4];
            }
#pragma unroll
            for (int j = 0; j < 2; j++) {
                int cb = warp_n * 16 + j * 8 + g;
                bf[j][0] = Vs[st][kk + t][cb];
                bf[j][1] = Vs[st][kk + t + 4][cb];
            }
#pragma unroll
            for (int i = 0; i < 2; i++)
#pragma unroll
                for (int j = 0; j < 2; j++)
                    mma8(acc[i][j], af[i], bf[j]);
        }
        if (nxt) {
#pragma unroll
            for (int i = 0; i < 2; i++) {
                int r = pr + i * 64;
                *(uint4*)&Ps[st ^ 1][r][pc] = make_uint4(f2tf(pp[i].x), f2tf(pp[i].y), f2tf(pp[i].z), f2tf(pp[i].w));
            }
            *(uint4*)&Vs[st ^ 1][vr][vc] = make_uint4(f2tf(pv.x), f2tf(pv.y), f2tf(pv.z), f2tf(pv.w));
        }
        __syncthreads();
        st ^= 1;
    }

    // Write ctx directly in concat layout (B, L, D) into g_q
#pragma unroll
    for (int i = 0; i < 2; i++) {
#pragma unroll
        for (int j = 0; j < 2; j++) {
            int l = m0 + warp_m * 32 + i * 16 + g;
            int c = warp_n * 16 + j * 8 + 2 * t;   // dh within [0,64)
            float* d0 = g_q + ((size_t)b * L_SZ + l) * D_SZ + h * DH_SZ + c;
            float* d1 = g_q + ((size_t)b * L_SZ + l + 8) * D_SZ + h * DH_SZ + c;
            *(float2*)d0 = make_float2(acc[i][j][0], acc[i][j][1]);
            *(float2*)d1 = make_float2(acc[i][j][2], acc[i][j][3]);
        }
    }
}

// ============================================================================
extern "C" void kernel_launch(void* const* d_in, const int* in_sizes, int n_in,
                              void* d_out, int out_size)
{
    (void)in_sizes; (void)n_in;
    const float* x  = (const float*)d_in[0];
    const float* Wq = (const float*)d_in[1];
    const float* Wk = (const float*)d_in[2];
    const float* Wv = (const float*)d_in[3];
    const float* Wo = (const float*)d_in[4];
    float* out = (float*)d_out;

    const int fb = ((size_t)out_size < OUT_ELEMS + ATTN_ELEMS) ? 1 : 0;

    cudaFuncSetAttribute(proj_kernel,   cudaFuncAttributeMaxDynamicSharedMemorySize, PROJ_SMEM);
    cudaFuncSetAttribute(stats_kernel,  cudaFuncAttributeMaxDynamicSharedMemorySize, STAT_SMEM);
    cudaFuncSetAttribute(scores_kernel, cudaFuncAttributeMaxDynamicSharedMemorySize, SC_SMEM);
    cudaFuncSetAttribute(av_kernel,     cudaFuncAttributeMaxDynamicSharedMemorySize, AV_SMEM);

    // 1. fused QKV projections (grid.z selects Wq/Wk/Wv)
    proj_kernel<<<dim3(8, 32, 3), 512, PROJ_SMEM>>>(x, Wq, Wk, Wv, nullptr, -1);
    // 2. per-row softmax stats (M, 1/Z) via QK^T recompute (no attn traffic)
    stats_kernel<<<dim3(16, 32), 512, STAT_SMEM>>>();
    // 3. scores + normalize: writes FINAL attn in one pass
    scores_kernel<<<dim3(16, 16, 32), 512, SC_SMEM>>>(out, fb);
    // 4. AV -> ctx (concat layout into g_q)
    av_kernel<<<dim3(16, 32), 512, AV_SMEM>>>(out, fb);
    // 5. out-projection
    proj_kernel<<<dim3(8, 32, 1), 512, PROJ_SMEM>>>(nullptr, Wo, nullptr, nullptr, out, 3);
}

// round 13
// speedup vs baseline: 1.0005x; 1.0005x over previous
#include <cuda_runtime.h>
#include <cuda_bf16.h>

// Problem: B=2, L=2048, D=1024, H=16, DH=64
// Output buffer: [output (B,L,D) = 4,194,304 f32][attn (B,H,L,L) = 134,217,728 f32]

#define B_SZ   2
#define L_SZ   2048
#define D_SZ   1024
#define H_SZ   16
#define DH_SZ  64

static constexpr size_t OUT_ELEMS  = (size_t)B_SZ * L_SZ * D_SZ;        // 4194304
static constexpr size_t ATTN_ELEMS = (size_t)B_SZ * H_SZ * L_SZ * L_SZ; // 134217728
static constexpr size_t QKV_ELEMS  = (size_t)B_SZ * H_SZ * L_SZ * DH_SZ;// 4194304

// Scratch (allocation-free rule: __device__ globals)
__device__ __align__(16) float g_q[QKV_ELEMS];   // reused as ctx concat (B,L,D) after AV
__device__ __align__(16) float g_k[QKV_ELEMS];
__device__ __align__(16) float g_v[QKV_ELEMS];
__device__ __align__(16) float2 g_stats[(size_t)B_SZ * H_SZ * L_SZ];  // {rowmax, 1/Z}
// Fallback attn scratch in case out_size only covers `output`
__device__ __align__(16) float g_attn_fb[ATTN_ELEMS];

__device__ __forceinline__ unsigned f2tf(float f) {
    unsigned u;
    asm("cvt.rna.tf32.f32 %0, %1;" : "=r"(u) : "f"(f));
    return u;
}

__device__ __forceinline__ void mma8(float c[4], const unsigned a[4], const unsigned b[2]) {
    asm volatile(
        "mma.sync.aligned.m16n8k8.row.col.f32.tf32.tf32.f32 "
        "{%0,%1,%2,%3}, {%4,%5,%6,%7}, {%8,%9}, {%0,%1,%2,%3};"
        : "+f"(c[0]), "+f"(c[1]), "+f"(c[2]), "+f"(c[3])
        : "r"(a[0]), "r"(a[1]), "r"(a[2]), "r"(a[3]), "r"(b[0]), "r"(b[1]));
}

// merge two (max, sumexp) pairs
__device__ __forceinline__ void mz_merge(float& m, float& z, float om, float oz) {
    float mn = fmaxf(m, om);
    z = z * __expf(m - mn) + oz * __expf(om - mn);
    m = mn;
}

// ============================================================================
// NT GEMM: C[M=4096, N=1024] = A[4096,1024] * W[1024,1024]^T, TF32 mma.
// 512 threads, 16 warps (4m x 4n), warp tile 32x32, BM=BN=128, BK=32.
// 2-stage smem double buffer with register prefetch.
// mode < 0: md = blockIdx.z in {0,1,2}: A = x, scatter into g_q/g_k/g_v (B,H,L,DH).
// mode == 3: A = g_q (ctx concat), plain row-major write to dst.
// ============================================================================
static constexpr int PROJ_SMEM = (2 * 128 * 36 * 2) * 4;  // 73728 B

__global__ void __launch_bounds__(512) proj_kernel(
    const float* __restrict__ Ain, const float* __restrict__ W0,
    const float* __restrict__ W1, const float* __restrict__ W2,
    float* __restrict__ dst, int mode)
{
    extern __shared__ unsigned sh[];
    unsigned (*As)[128][36] = (unsigned(*)[128][36])sh;
    unsigned (*Ws)[128][36] = (unsigned(*)[128][36])(sh + 2 * 128 * 36);

    const int md = (mode < 0) ? (int)blockIdx.z : mode;
    const float* W = (md == 1) ? W1 : (md == 2) ? W2 : W0;
    const float* A = (md == 3) ? (const float*)g_q : Ain;

    const int tid  = threadIdx.x;
    const int wid  = tid >> 5;
    const int lane = tid & 31;
    const int g = lane >> 2, t = lane & 3;
    const int warp_m = wid & 3, warp_n = wid >> 2;
    const int m0 = blockIdx.y * 128;
    const int n0 = blockIdx.x * 128;

    const int lr = tid >> 3;          // 0..63 (row within stage, +64 for i=1)
    const int lc = (tid & 7) << 2;    // 0..28

    float acc[2][4][4];
#pragma unroll
    for (int i = 0; i < 2; i++)
#pragma unroll
        for (int j = 0; j < 4; j++)
#pragma unroll
            for (int c = 0; c < 4; c++) acc[i][j][c] = 0.f;

    // preload stage 0
#pragma unroll
    for (int i = 0; i < 2; i++) {
        int r = lr + i * 64;
        float4 fa = *(const float4*)(A + (size_t)(m0 + r) * 1024 + lc);
        float4 fw = *(const float4*)(W + (size_t)(n0 + r) * 1024 + lc);
        *(uint4*)&As[0][r][lc] = make_uint4(f2tf(fa.x), f2tf(fa.y), f2tf(fa.z), f2tf(fa.w));
        *(uint4*)&Ws[0][r][lc] = make_uint4(f2tf(fw.x), f2tf(fw.y), f2tf(fw.z), f2tf(fw.w));
    }
    __syncthreads();

    int st = 0;
    for (int k0 = 0; k0 < 1024; k0 += 32) {
        const bool nxt = (k0 + 32) < 1024;
        float4 pa[2], pw[2];
        if (nxt) {
#pragma unroll
            for (int i = 0; i < 2; i++) {
                int r = lr + i * 64;
                pa[i] = *(const float4*)(A + (size_t)(m0 + r) * 1024 + k0 + 32 + lc);
                pw[i] = *(const float4*)(W + (size_t)(n0 + r) * 1024 + k0 + 32 + lc);
            }
        }
#pragma unroll
        for (int kk = 0; kk < 32; kk += 8) {
            unsigned af[2][4], bf[4][2];
#pragma unroll
            for (int i = 0; i < 2; i++) {
                int rb = warp_m * 32 + i * 16 + g;
                af[i][0] = As[st][rb][kk + t];
                af[i][1] = As[st][rb + 8][kk + t];
                af[i][2] = As[st][rb][kk + t + 4];
                af[i][3] = As[st][rb + 8][kk + t + 4];
            }
#pragma unroll
            for (int j = 0; j < 4; j++) {
                int cb = warp_n * 32 + j * 8 + g;
                bf[j][0] = Ws[st][cb][kk + t];
                bf[j][1] = Ws[st][cb][kk + t + 4];
            }
#pragma unroll
            for (int i = 0; i < 2; i++)
#pragma unroll
                for (int j = 0; j < 4; j++)
                    mma8(acc[i][j], af[i], bf[j]);
        }
        if (nxt) {
#pragma unroll
            for (int i = 0; i < 2; i++) {
                int r = lr + i * 64;
                *(uint4*)&As[st ^ 1][r][lc] = make_uint4(f2tf(pa[i].x), f2tf(pa[i].y), f2tf(pa[i].z), f2tf(pa[i].w));
                *(uint4*)&Ws[st ^ 1][r][lc] = make_uint4(f2tf(pw[i].x), f2tf(pw[i].y), f2tf(pw[i].z), f2tf(pw[i].w));
            }
        }
        __syncthreads();
        st ^= 1;
    }

    // Epilogue
#pragma unroll
    for (int i = 0; i < 2; i++) {
#pragma unroll
        for (int j = 0; j < 4; j++) {
            int r0 = m0 + warp_m * 32 + i * 16 + g;
            int c0 = n0 + warp_n * 32 + j * 8 + 2 * t;
            float2 lo = make_float2(acc[i][j][0], acc[i][j][1]);
            float2 hi = make_float2(acc[i][j][2], acc[i][j][3]);
            if (md == 3) {
                *(float2*)(dst + (size_t)r0 * 1024 + c0) = lo;
                *(float2*)(dst + (size_t)(r0 + 8) * 1024 + c0) = hi;
            } else {
                float* qkv = (md == 0) ? g_q : (md == 1) ? g_k : g_v;
                size_t i0 = ((size_t)((r0 >> 11) * H_SZ + (c0 >> 6)) * L_SZ + (r0 & 2047)) * DH_SZ + (c0 & 63);
                *(float2*)(qkv + i0) = lo;
                int r1 = r0 + 8;
                size_t i1 = ((size_t)((r1 >> 11) * H_SZ + (c0 >> 6)) * L_SZ + (r1 & 2047)) * DH_SZ + (c0 & 63);
                *(float2*)(qkv + i1) = hi;
            }
        }
    }
}

// ============================================================================
// Stats (flash pass-1): per (b,h, row-block 128), recompute S = Q K^T * 0.125
// streaming K in 128-col tiles; produce per-row (max M, 1/Z), Z = sum exp(s-M).
// Same mma fragment order as the scores kernel -> bit-identical s values.
// ============================================================================
static constexpr int STAT_SMEM = (128 * 68 + 2 * 128 * 68 + 4 * 128 * 2) * 4; // 108544 B

__global__ void __launch_bounds__(512) stats_kernel()
{
    extern __shared__ unsigned sh[];
    unsigned (*Qs)[68]       = (unsigned(*)[68])sh;
    unsigned (*Ks)[128][68]  = (unsigned(*)[128][68])(sh + 128 * 68);
    float    (*red)[128][2]  = (float(*)[128][2])(sh + 128 * 68 + 2 * 128 * 68);

    const int tid  = threadIdx.x;
    const int wid  = tid >> 5;
    const int lane = tid & 31;
    const int g = lane >> 2, t = lane & 3;
    const int warp_m = wid & 3, warp_n = wid >> 2;
    const int m0 = blockIdx.x * 128;
    const int bh = blockIdx.y;

    const float* Qb = g_q + (size_t)bh * L_SZ * DH_SZ;
    const float* Kb = g_k + (size_t)bh * L_SZ * DH_SZ;

    const int lr = tid >> 4;          // 0..31 (+32 per i), 16 float4 per 64-wide row
    const int lc = (tid & 15) << 2;

    // Load Q tile (128x64) once, and K tile 0
#pragma unroll
    for (int i = 0; i < 4; i++) {
        int r = lr + i * 32;
        float4 fq = *(const float4*)(Qb + (size_t)(m0 + r) * DH_SZ + lc);
        *(uint4*)&Qs[r][lc] = make_uint4(f2tf(fq.x), f2tf(fq.y), f2tf(fq.z), f2tf(fq.w));
        float4 fk = *(const float4*)(Kb + (size_t)r * DH_SZ + lc);
        *(uint4*)&Ks[0][r][lc] = make_uint4(f2tf(fk.x), f2tf(fk.y), f2tf(fk.z), f2tf(fk.w));
    }
    __syncthreads();

    float m_[4] = {-1e30f, -1e30f, -1e30f, -1e30f};
    float z_[4] = {0.f, 0.f, 0.f, 0.f};

    int st = 0;
    for (int n0 = 0; n0 < L_SZ; n0 += 128) {
        const bool nxt = (n0 + 128) < L_SZ;
        float4 pk[4];
        if (nxt) {
#pragma unroll
            for (int i = 0; i < 4; i++) {
                int r = lr + i * 32;
                pk[i] = *(const float4*)(Kb + (size_t)(n0 + 128 + r) * DH_SZ + lc);
            }
        }
        float acc[2][4][4];
#pragma unroll
        for (int i = 0; i < 2; i++)
#pragma unroll
            for (int j = 0; j < 4; j++)
#pragma unroll
                for (int c = 0; c < 4; c++) acc[i][j][c] = 0.f;

#pragma unroll
        for (int kk = 0; kk < 64; kk += 8) {
            unsigned af[2][4], bf[4][2];
#pragma unroll
            for (int i = 0; i < 2; i++) {
                int rb = warp_m * 32 + i * 16 + g;
                af[i][0] = Qs[rb][kk + t];
                af[i][1] = Qs[rb + 8][kk + t];
                af[i][2] = Qs[rb][kk + t + 4];
                af[i][3] = Qs[rb + 8][kk + t + 4];
            }
#pragma unroll
            for (int j = 0; j < 4; j++) {
                int cb = warp_n * 32 + j * 8 + g;
                bf[j][0] = Ks[st][cb][kk + t];
                bf[j][1] = Ks[st][cb][kk + t + 4];
            }
#pragma unroll
            for (int i = 0; i < 2; i++)
#pragma unroll
                for (int j = 0; j < 4; j++)
                    mma8(acc[i][j], af[i], bf[j]);
        }
        if (nxt) {
#pragma unroll
            for (int i = 0; i < 4; i++) {
                int r = lr + i * 32;
                *(uint4*)&Ks[st ^ 1][r][lc] = make_uint4(f2tf(pk[i].x), f2tf(pk[i].y), f2tf(pk[i].z), f2tf(pk[i].w));
            }
        }
        // online (m,z) update from this tile (register-only)
#pragma unroll
        for (int i = 0; i < 2; i++) {
#pragma unroll
            for (int half = 0; half < 2; half++) {
                int ri = i * 2 + half;
                float v[8];
#pragma unroll
                for (int j = 0; j < 4; j++) {
                    v[2 * j]     = acc[i][j][half * 2]     * 0.125f;
                    v[2 * j + 1] = acc[i][j][half * 2 + 1] * 0.125f;
                }
                float tm = v[0];
#pragma unroll
                for (int k = 1; k < 8; k++) tm = fmaxf(tm, v[k]);
                float mn = fmaxf(m_[ri], tm);
                float zs = 0.f;
#pragma unroll
                for (int k = 0; k < 8; k++) zs += __expf(v[k] - mn);
                z_[ri] = z_[ri] * __expf(m_[ri] - mn) + zs;
                m_[ri] = mn;
            }
        }
        __syncthreads();
        st ^= 1;
    }

    // combine across the 4 t-lanes sharing the same rows
#pragma unroll
    for (int ri = 0; ri < 4; ri++) {
#pragma unroll
        for (int o = 1; o < 4; o <<= 1) {
            float om = __shfl_xor_sync(0xffffffffu, m_[ri], o);
            float oz = __shfl_xor_sync(0xffffffffu, z_[ri], o);
            mz_merge(m_[ri], z_[ri], om, oz);
        }
    }
    if (t == 0) {
#pragma unroll
        for (int i = 0; i < 2; i++) {
            int rl = warp_m * 32 + i * 16 + g;
            red[warp_n][rl][0]     = m_[i * 2];
            red[warp_n][rl][1]     = z_[i * 2];
            red[warp_n][rl + 8][0] = m_[i * 2 + 1];
            red[warp_n][rl + 8][1] = z_[i * 2 + 1];
        }
    }
    __syncthreads();
    if (tid < 128) {
        float M = red[0][tid][0], Z = red[0][tid][1];
#pragma unroll
        for (int w = 1; w < 4; w++) mz_merge(M, Z, red[w][tid][0], red[w][tid][1]);
        g_stats[(size_t)bh * L_SZ + m0 + tid] = make_float2(M, 1.0f / Z);
    }
}

// ============================================================================
// Scores + normalize: per (b,h), attn = exp(QK^T * 0.125 - M) * invZ (final!)
// BM=BN=128, K=64 all-in-smem. 512 threads, warps 4x4, tile 32x32.
// ============================================================================
static constexpr int SC_SMEM = (2 * 128 * 68 + 2 * 128) * 4; // 70656 B

__global__ void __launch_bounds__(512) scores_kernel(float* __restrict__ out, int fb)
{
    extern __shared__ unsigned sh[];
    unsigned (*Qs)[68] = (unsigned(*)[68])sh;
    unsigned (*Ks)[68] = (unsigned(*)[68])(sh + 128 * 68);
    float* sM = (float*)(sh + 2 * 128 * 68);
    float* sI = sM + 128;

    float* attn = fb ? g_attn_fb : out + OUT_ELEMS;
    const int bh = blockIdx.z;
    const float* Qb = g_q + (size_t)bh * L_SZ * DH_SZ;
    const float* Kb = g_k + (size_t)bh * L_SZ * DH_SZ;

    const int tid  = threadIdx.x;
    const int wid  = tid >> 5;
    const int lane = tid & 31;
    const int g = lane >> 2, t = lane & 3;
    const int warp_m = wid & 3, warp_n = wid >> 2;
    const int m0 = blockIdx.y * 128;
    const int n0 = blockIdx.x * 128;

    const int lr = tid >> 4;
    const int lc = (tid & 15) << 2;

    if (tid < 128) {
        float2 s = g_stats[(size_t)bh * L_SZ + m0 + tid];
        sM[tid] = s.x; sI[tid] = s.y;
    }
#pragma unroll
    for (int i = 0; i < 4; i++) {
        int r = lr + i * 32;
        float4 fq = *(const float4*)(Qb + (size_t)(m0 + r) * DH_SZ + lc);
        *(uint4*)&Qs[r][lc] = make_uint4(f2tf(fq.x), f2tf(fq.y), f2tf(fq.z), f2tf(fq.w));
        float4 fk = *(const float4*)(Kb + (size_t)(n0 + r) * DH_SZ + lc);
        *(uint4*)&Ks[r][lc] = make_uint4(f2tf(fk.x), f2tf(fk.y), f2tf(fk.z), f2tf(fk.w));
    }
    __syncthreads();

    float acc[2][4][4];
#pragma unroll
    for (int i = 0; i < 2; i++)
#pragma unroll
        for (int j = 0; j < 4; j++)
#pragma unroll
            for (int c = 0; c < 4; c++) acc[i][j][c] = 0.f;

#pragma unroll
    for (int kk = 0; kk < 64; kk += 8) {
        unsigned af[2][4], bf[4][2];
#pragma unroll
        for (int i = 0; i < 2; i++) {
            int rb = warp_m * 32 + i * 16 + g;
            af[i][0] = Qs[rb][kk + t];
            af[i][1] = Qs[rb + 8][kk + t];
            af[i][2] = Qs[rb][kk + t + 4];
            af[i][3] = Qs[rb + 8][kk + t + 4];
        }
#pragma unroll
        for (int j = 0; j < 4; j++) {
            int cb = warp_n * 32 + j * 8 + g;
            bf[j][0] = Ks[cb][kk + t];
            bf[j][1] = Ks[cb][kk + t + 4];
        }
#pragma unroll
        for (int i = 0; i < 2; i++)
#pragma unroll
            for (int j = 0; j < 4; j++)
                mma8(acc[i][j], af[i], bf[j]);
    }

    float* Sb = attn + (size_t)bh * L_SZ * L_SZ;
#pragma unroll
    for (int i = 0; i < 2; i++) {
        int rl = warp_m * 32 + i * 16 + g;
        float M0 = sM[rl],     I0 = sI[rl];
        float M1 = sM[rl + 8], I1 = sI[rl + 8];
#pragma unroll
        for (int j = 0; j < 4; j++) {
            int r0 = m0 + rl;
            int c0 = n0 + warp_n * 32 + j * 8 + 2 * t;
            float2 lo = make_float2(__expf(acc[i][j][0] * 0.125f - M0) * I0,
                                    __expf(acc[i][j][1] * 0.125f - M0) * I0);
            float2 hi = make_float2(__expf(acc[i][j][2] * 0.125f - M1) * I1,
                                    __expf(acc[i][j][3] * 0.125f - M1) * I1);
            *(float2*)(Sb + (size_t)r0 * L_SZ + c0) = lo;
            *(float2*)(Sb + (size_t)(r0 + 8) * L_SZ + c0) = hi;
        }
    }
}

// ============================================================================
// AV: per (b,h), ctx[2048,64] = P[2048,2048] * V[2048,64]
// 512 threads, warps 4(m) x 4(n), warp tile 32x16, BK=32, double-buffered.
// Epilogue writes concat layout (B,L,D) into g_q.
// ============================================================================
static constexpr int AV_SMEM = (2 * 128 * 36 + 2 * 32 * 68) * 4; // 54272 B

__global__ void __launch_bounds__(512) av_kernel(float* __restrict__ out, int fb)
{
    extern __shared__ unsigned sh[];
    unsigned (*Ps)[128][36] = (unsigned(*)[128][36])sh;
    unsigned (*Vs)[32][68]  = (unsigned(*)[32][68])(sh + 2 * 128 * 36);

    float* attn = fb ? g_attn_fb : out + OUT_ELEMS;
    const int bh = blockIdx.y;
    const int m0 = blockIdx.x * 128;
    const int b  = bh >> 4;
    const int h  = bh & 15;

    const int tid  = threadIdx.x;
    const int wid  = tid >> 5;
    const int lane = tid & 31;
    const int g = lane >> 2, t = lane & 3;
    const int warp_m = wid & 3, warp_n = wid >> 2;

    const float* Pb = attn + (size_t)bh * L_SZ * L_SZ + (size_t)m0 * L_SZ;
    const float* Vb = g_v + (size_t)bh * L_SZ * DH_SZ;

    const int pr = tid >> 3;          // P: 0..63 (+64), 8 float4 per 32-wide row
    const int pc = (tid & 7) << 2;
    const int vr = tid >> 4;          // V: 0..31, 16 float4 per 64-wide row
    const int vc = (tid & 15) << 2;

    float acc[2][2][4];
#pragma unroll
    for (int i = 0; i < 2; i++)
#pragma unroll
        for (int j = 0; j < 2; j++)
#pragma unroll
            for (int c = 0; c < 4; c++) acc[i][j][c] = 0.f;

    // preload stage 0
#pragma unroll
    for (int i = 0; i < 2; i++) {
        int r = pr + i * 64;
        float4 f = *(const float4*)(Pb + (size_t)r * L_SZ + pc);
        *(uint4*)&Ps[0][r][pc] = make_uint4(f2tf(f.x), f2tf(f.y), f2tf(f.z), f2tf(f.w));
    }
    {
        float4 f = *(const float4*)(Vb + (size_t)vr * DH_SZ + vc);
        *(uint4*)&Vs[0][vr][vc] = make_uint4(f2tf(f.x), f2tf(f.y), f2tf(f.z), f2tf(f.w));
    }
    __syncthreads();

    int st = 0;
    for (int k0 = 0; k0 < L_SZ; k0 += 32) {
        const bool nxt = (k0 + 32) < L_SZ;
        float4 pp[2], pv;
        if (nxt) {
#pragma unroll
            for (int i = 0; i < 2; i++) {
                int r = pr + i * 64;
                pp[i] = *(const float4*)(Pb + (size_t)r * L_SZ + k0 + 32 + pc);
            }
            pv = *(const float4*)(Vb + (size_t)(k0 + 32 + vr) * DH_SZ + vc);
        }
#pragma unroll
        for (int kk = 0; kk < 32; kk += 8) {
            unsigned af[2][4], bf[2][2];
#pragma unroll
            for (int i = 0; i < 2; i++) {
                int rb = warp_m * 32 + i * 16 + g;
                af[i][0] = Ps[st][rb][kk + t];
                af[i][1] = Ps[st][rb + 8][kk + t];
                af[i][2] = Ps[st][rb][kk + t + 4];
                af[i][3] = Ps[st][rb + 8][kk + t + 4];
            }
#pragma unroll
            for (int j = 0; j < 2; j++) {
                int cb = warp_n * 16 + j * 8 + g;
                bf[j][0] = Vs[st][kk + t][cb];
                bf[j][1] = Vs[st][kk + t + 4][cb];
            }
#pragma unroll
            for (int i = 0; i < 2; i++)
#pragma unroll
                for (int j = 0; j < 2; j++)
                    mma8(acc[i][j], af[i], bf[j]);
        }
        if (nxt) {
#pragma unroll
            for (int i = 0; i < 2; i++) {
                int r = pr + i * 64;
                *(uint4*)&Ps[st ^ 1][r][pc] = make_uint4(f2tf(pp[i].x), f2tf(pp[i].y), f2tf(pp[i].z), f2tf(pp[i].w));
            }
            *(uint4*)&Vs[st ^ 1][vr][vc] = make_uint4(f2tf(pv.x), f2tf(pv.y), f2tf(pv.z), f2tf(pv.w));
        }
        __syncthreads();
        st ^= 1;
    }

    // Write ctx directly in concat layout (B, L, D) into g_q
#pragma unroll
    for (int i = 0; i < 2; i++) {
#pragma unroll
        for (int j = 0; j < 2; j++) {
            int l = m0 + warp_m * 32 + i * 16 + g;
            int c = warp_n * 16 + j * 8 + 2 * t;   // dh within [0,64)
            float* d0 = g_q + ((size_t)b * L_SZ + l) * D_SZ + h * DH_SZ + c;
            float* d1 = g_q + ((size_t)b * L_SZ + l + 8) * D_SZ + h * DH_SZ + c;
            *(float2*)d0 = make_float2(acc[i][j][0], acc[i][j][1]);
            *(float2*)d1 = make_float2(acc[i][j][2], acc[i][j][3]);
        }
    }
}

// ============================================================================
extern "C" void kernel_launch(void* const* d_in, const int* in_sizes, int n_in,
                              void* d_out, int out_size)
{
    (void)in_sizes; (void)n_in;
    const float* x  = (const float*)d_in[0];
    const float* Wq = (const float*)d_in[1];
    const float* Wk = (const float*)d_in[2];
    const float* Wv = (const float*)d_in[3];
    const float* Wo = (const float*)d_in[4];
    float* out = (float*)d_out;

    const int fb = ((size_t)out_size < OUT_ELEMS + ATTN_ELEMS) ? 1 : 0;

    cudaFuncSetAttribute(proj_kernel,   cudaFuncAttributeMaxDynamicSharedMemorySize, PROJ_SMEM);
    cudaFuncSetAttribute(stats_kernel,  cudaFuncAttributeMaxDynamicSharedMemorySize, STAT_SMEM);
    cudaFuncSetAttribute(scores_kernel, cudaFuncAttributeMaxDynamicSharedMemorySize, SC_SMEM);
    cudaFuncSetAttribute(av_kernel,     cudaFuncAttributeMaxDynamicSharedMemorySize, AV_SMEM);

    // 1. fused QKV projections (grid.z selects Wq/Wk/Wv)
    proj_kernel<<<dim3(8, 32, 3), 512, PROJ_SMEM>>>(x, Wq, Wk, Wv, nullptr, -1);
    // 2. per-row softmax stats (M, 1/Z) via QK^T recompute (no attn traffic)
    stats_kernel<<<dim3(16, 32), 512, STAT_SMEM>>>();
    // 3. scores + normalize: writes FINAL attn in one pass
    scores_kernel<<<dim3(16, 16, 32), 512, SC_SMEM>>>(out, fb);
    // 4. AV -> ctx (concat layout into g_q)
    av_kernel<<<dim3(16, 32), 512, AV_SMEM>>>(out, fb);
    // 5. out-projection
    proj_kernel<<<dim3(8, 32, 1), 512, PROJ_SMEM>>>(nullptr, Wo, nullptr, nullptr, out, 3);
}

// round 15
// speedup vs baseline: 1.0122x; 1.0117x over previous
#include <cuda_runtime.h>
#include <cuda_bf16.h>

// Problem: B=2, L=2048, D=1024, H=16, DH=64
// Output buffer: [output (B,L,D) = 4,194,304 f32][attn (B,H,L,L) = 134,217,728 f32]

#define B_SZ   2
#define L_SZ   2048
#define D_SZ   1024
#define H_SZ   16
#define DH_SZ  64

static constexpr size_t OUT_ELEMS  = (size_t)B_SZ * L_SZ * D_SZ;        // 4194304
static constexpr size_t ATTN_ELEMS = (size_t)B_SZ * H_SZ * L_SZ * L_SZ; // 134217728
static constexpr size_t QKV_ELEMS  = (size_t)B_SZ * H_SZ * L_SZ * DH_SZ;// 4194304

// Scratch (allocation-free rule: __device__ globals)
__device__ __align__(16) float g_q[QKV_ELEMS];
__device__ __align__(16) float g_k[QKV_ELEMS];
__device__ __align__(16) float g_v[QKV_ELEMS];
__device__ __align__(16) float g_ctx[OUT_ELEMS];                      // ctx concat (B,L,D)
__device__ __align__(16) float2 g_stats[(size_t)B_SZ * H_SZ * L_SZ];  // {rowmax, 1/Z}
// Fallback attn scratch in case out_size only covers `output`
__device__ __align__(16) float g_attn_fb[ATTN_ELEMS];

__device__ __forceinline__ unsigned f2tf(float f) {
    unsigned u;
    asm("cvt.rna.tf32.f32 %0, %1;" : "=r"(u) : "f"(f));
    return u;
}

__device__ __forceinline__ void mma8(float c[4], const unsigned a[4], const unsigned b[2]) {
    asm volatile(
        "mma.sync.aligned.m16n8k8.row.col.f32.tf32.tf32.f32 "
        "{%0,%1,%2,%3}, {%4,%5,%6,%7}, {%8,%9}, {%0,%1,%2,%3};"
        : "+f"(c[0]), "+f"(c[1]), "+f"(c[2]), "+f"(c[3])
        : "r"(a[0]), "r"(a[1]), "r"(a[2]), "r"(a[3]), "r"(b[0]), "r"(b[1]));
}

// merge two (max, sumexp) pairs
__device__ __forceinline__ void mz_merge(float& m, float& z, float om, float oz) {
    float mn = fmaxf(m, om);
    z = z * __expf(m - mn) + oz * __expf(om - mn);
    m = mn;
}

// ============================================================================
// NT GEMM: C[M=4096, N=1024] = A[4096,1024] * W[1024,1024]^T, TF32 mma.
// 512 threads, 16 warps (4m x 4n), warp tile 32x32, BM=BN=128, BK=32.
// 2-stage smem double buffer with register prefetch.
// mode < 0: md = blockIdx.z in {0,1,2}: A = x, scatter into g_q/g_k/g_v (B,H,L,DH).
// mode == 3: A = g_ctx (concat), plain row-major write to dst.
// ============================================================================
static constexpr int PROJ_SMEM = (2 * 128 * 36 * 2) * 4;  // 73728 B

__global__ void __launch_bounds__(512) proj_kernel(
    const float* __restrict__ Ain, const float* __restrict__ W0,
    const float* __restrict__ W1, const float* __restrict__ W2,
    float* __restrict__ dst, int mode)
{
    extern __shared__ unsigned sh[];
    unsigned (*As)[128][36] = (unsigned(*)[128][36])sh;
    unsigned (*Ws)[128][36] = (unsigned(*)[128][36])(sh + 2 * 128 * 36);

    const int md = (mode < 0) ? (int)blockIdx.z : mode;
    const float* W = (md == 1) ? W1 : (md == 2) ? W2 : W0;
    const float* A = (md == 3) ? (const float*)g_ctx : Ain;

    const int tid  = threadIdx.x;
    const int wid  = tid >> 5;
    const int lane = tid & 31;
    const int g = lane >> 2, t = lane & 3;
    const int warp_m = wid & 3, warp_n = wid >> 2;
    const int m0 = blockIdx.y * 128;
    const int n0 = blockIdx.x * 128;

    const int lr = tid >> 3;          // 0..63 (row within stage, +64 for i=1)
    const int lc = (tid & 7) << 2;    // 0..28

    float acc[2][4][4];
#pragma unroll
    for (int i = 0; i < 2; i++)
#pragma unroll
        for (int j = 0; j < 4; j++)
#pragma unroll
            for (int c = 0; c < 4; c++) acc[i][j][c] = 0.f;

    // preload stage 0
#pragma unroll
    for (int i = 0; i < 2; i++) {
        int r = lr + i * 64;
        float4 fa = *(const float4*)(A + (size_t)(m0 + r) * 1024 + lc);
        float4 fw = *(const float4*)(W + (size_t)(n0 + r) * 1024 + lc);
        *(uint4*)&As[0][r][lc] = make_uint4(f2tf(fa.x), f2tf(fa.y), f2tf(fa.z), f2tf(fa.w));
        *(uint4*)&Ws[0][r][lc] = make_uint4(f2tf(fw.x), f2tf(fw.y), f2tf(fw.z), f2tf(fw.w));
    }
    __syncthreads();

    int st = 0;
    for (int k0 = 0; k0 < 1024; k0 += 32) {
        const bool nxt = (k0 + 32) < 1024;
        float4 pa[2], pw[2];
        if (nxt) {
#pragma unroll
            for (int i = 0; i < 2; i++) {
                int r = lr + i * 64;
                pa[i] = *(const float4*)(A + (size_t)(m0 + r) * 1024 + k0 + 32 + lc);
                pw[i] = *(const float4*)(W + (size_t)(n0 + r) * 1024 + k0 + 32 + lc);
            }
        }
#pragma unroll
        for (int kk = 0; kk < 32; kk += 8) {
            unsigned af[2][4], bf[4][2];
#pragma unroll
            for (int i = 0; i < 2; i++) {
                int rb = warp_m * 32 + i * 16 + g;
                af[i][0] = As[st][rb][kk + t];
                af[i][1] = As[st][rb + 8][kk + t];
                af[i][2] = As[st][rb][kk + t + 4];
                af[i][3] = As[st][rb + 8][kk + t + 4];
            }
#pragma unroll
            for (int j = 0; j < 4; j++) {
                int cb = warp_n * 32 + j * 8 + g;
                bf[j][0] = Ws[st][cb][kk + t];
                bf[j][1] = Ws[st][cb][kk + t + 4];
            }
#pragma unroll
            for (int i = 0; i < 2; i++)
#pragma unroll
                for (int j = 0; j < 4; j++)
                    mma8(acc[i][j], af[i], bf[j]);
        }
        if (nxt) {
#pragma unroll
            for (int i = 0; i < 2; i++) {
                int r = lr + i * 64;
                *(uint4*)&As[st ^ 1][r][lc] = make_uint4(f2tf(pa[i].x), f2tf(pa[i].y), f2tf(pa[i].z), f2tf(pa[i].w));
                *(uint4*)&Ws[st ^ 1][r][lc] = make_uint4(f2tf(pw[i].x), f2tf(pw[i].y), f2tf(pw[i].z), f2tf(pw[i].w));
            }
        }
        __syncthreads();
        st ^= 1;
    }

    // Epilogue
#pragma unroll
    for (int i = 0; i < 2; i++) {
#pragma unroll
        for (int j = 0; j < 4; j++) {
            int r0 = m0 + warp_m * 32 + i * 16 + g;
            int c0 = n0 + warp_n * 32 + j * 8 + 2 * t;
            float2 lo = make_float2(acc[i][j][0], acc[i][j][1]);
            float2 hi = make_float2(acc[i][j][2], acc[i][j][3]);
            if (md == 3) {
                *(float2*)(dst + (size_t)r0 * 1024 + c0) = lo;
                *(float2*)(dst + (size_t)(r0 + 8) * 1024 + c0) = hi;
            } else {
                float* qkv = (md == 0) ? g_q : (md == 1) ? g_k : g_v;
                size_t i0 = ((size_t)((r0 >> 11) * H_SZ + (c0 >> 6)) * L_SZ + (r0 & 2047)) * DH_SZ + (c0 & 63);
                *(float2*)(qkv + i0) = lo;
                int r1 = r0 + 8;
                size_t i1 = ((size_t)((r1 >> 11) * H_SZ + (c0 >> 6)) * L_SZ + (r1 & 2047)) * DH_SZ + (c0 & 63);
                *(float2*)(qkv + i1) = hi;
            }
        }
    }
}

// ============================================================================
// Stats (flash pass-1): per (b,h, row-block 128), recompute S = Q K^T * 0.125
// streaming K in 128-col tiles; produce per-row (max M, 1/Z), Z = sum exp(s-M).
// Same mma fragment order as the fused attn kernel -> identical s values.
// ============================================================================
static constexpr int STAT_SMEM = (128 * 68 + 2 * 128 * 68 + 4 * 128 * 2) * 4; // 108544 B

__global__ void __launch_bounds__(512) stats_kernel()
{
    extern __shared__ unsigned sh[];
    unsigned (*Qs)[68]       = (unsigned(*)[68])sh;
    unsigned (*Ks)[128][68]  = (unsigned(*)[128][68])(sh + 128 * 68);
    float    (*red)[128][2]  = (float(*)[128][2])(sh + 128 * 68 + 2 * 128 * 68);

    const int tid  = threadIdx.x;
    const int lane = tid & 31;
    const int wid  = tid >> 5;
    const int g = lane >> 2, t = lane & 3;
    const int warp_m = wid & 3, warp_n = wid >> 2;
    const int m0 = blockIdx.x * 128;
    const int bh = blockIdx.y;

    const float* Qb = g_q + (size_t)bh * L_SZ * DH_SZ;
    const float* Kb = g_k + (size_t)bh * L_SZ * DH_SZ;

    const int lr = tid >> 4;          // 0..31 (+32 per i), 16 float4 per 64-wide row
    const int lc = (tid & 15) << 2;

#pragma unroll
    for (int i = 0; i < 4; i++) {
        int r = lr + i * 32;
        float4 fq = *(const float4*)(Qb + (size_t)(m0 + r) * DH_SZ + lc);
        *(uint4*)&Qs[r][lc] = make_uint4(f2tf(fq.x), f2tf(fq.y), f2tf(fq.z), f2tf(fq.w));
        float4 fk = *(const float4*)(Kb + (size_t)r * DH_SZ + lc);
        *(uint4*)&Ks[0][r][lc] = make_uint4(f2tf(fk.x), f2tf(fk.y), f2tf(fk.z), f2tf(fk.w));
    }
    __syncthreads();

    float m_[4] = {-1e30f, -1e30f, -1e30f, -1e30f};
    float z_[4] = {0.f, 0.f, 0.f, 0.f};

    int st = 0;
    for (int n0 = 0; n0 < L_SZ; n0 += 128) {
        const bool nxt = (n0 + 128) < L_SZ;
        float4 pk[4];
        if (nxt) {
#pragma unroll
            for (int i = 0; i < 4; i++) {
                int r = lr + i * 32;
                pk[i] = *(const float4*)(Kb + (size_t)(n0 + 128 + r) * DH_SZ + lc);
            }
        }
        float acc[2][4][4];
#pragma unroll
        for (int i = 0; i < 2; i++)
#pragma unroll
            for (int j = 0; j < 4; j++)
#pragma unroll
                for (int c = 0; c < 4; c++) acc[i][j][c] = 0.f;

#pragma unroll
        for (int kk = 0; kk < 64; kk += 8) {
            unsigned af[2][4], bf[4][2];
#pragma unroll
            for (int i = 0; i < 2; i++) {
                int rb = warp_m * 32 + i * 16 + g;
                af[i][0] = Qs[rb][kk + t];
                af[i][1] = Qs[rb + 8][kk + t];
                af[i][2] = Qs[rb][kk + t + 4];
                af[i][3] = Qs[rb + 8][kk + t + 4];
            }
#pragma unroll
            for (int j = 0; j < 4; j++) {
                int cb = warp_n * 32 + j * 8 + g;
                bf[j][0] = Ks[st][cb][kk + t];
                bf[j][1] = Ks[st][cb][kk + t + 4];
            }
#pragma unroll
            for (int i = 0; i < 2; i++)
#pragma unroll
                for (int j = 0; j < 4; j++)
                    mma8(acc[i][j], af[i], bf[j]);
        }
        if (nxt) {
#pragma unroll
            for (int i = 0; i < 4; i++) {
                int r = lr + i * 32;
                *(uint4*)&Ks[st ^ 1][r][lc] = make_uint4(f2tf(pk[i].x), f2tf(pk[i].y), f2tf(pk[i].z), f2tf(pk[i].w));
            }
        }
#pragma unroll
        for (int i = 0; i < 2; i++) {
#pragma unroll
            for (int half = 0; half < 2; half++) {
                int ri = i * 2 + half;
                float v[8];
#pragma unroll
                for (int j = 0; j < 4; j++) {
                    v[2 * j]     = acc[i][j][half * 2]     * 0.125f;
                    v[2 * j + 1] = acc[i][j][half * 2 + 1] * 0.125f;
                }
                float tm = v[0];
#pragma unroll
                for (int k = 1; k < 8; k++) tm = fmaxf(tm, v[k]);
                float mn = fmaxf(m_[ri], tm);
                float zs = 0.f;
#pragma unroll
                for (int k = 0; k < 8; k++) zs += __expf(v[k] - mn);
                z_[ri] = z_[ri] * __expf(m_[ri] - mn) + zs;
                m_[ri] = mn;
            }
        }
        __syncthreads();
        st ^= 1;
    }

#pragma unroll
    for (int ri = 0; ri < 4; ri++) {
#pragma unroll
        for (int o = 1; o < 4; o <<= 1) {
            float om = __shfl_xor_sync(0xffffffffu, m_[ri], o);
            float oz = __shfl_xor_sync(0xffffffffu, z_[ri], o);
            mz_merge(m_[ri], z_[ri], om, oz);
        }
    }
    if (t == 0) {
#pragma unroll
        for (int i = 0; i < 2; i++) {
            int rl = warp_m * 32 + i * 16 + g;
            red[warp_n][rl][0]     = m_[i * 2];
            red[warp_n][rl][1]     = z_[i * 2];
            red[warp_n][rl + 8][0] = m_[i * 2 + 1];
            red[warp_n][rl + 8][1] = z_[i * 2 + 1];
        }
    }
    __syncthreads();
    if (tid < 128) {
        float M = red[0][tid][0], Z = red[0][tid][1];
#pragma unroll
        for (int w = 1; w < 4; w++) mz_merge(M, Z, red[w][tid][0], red[w][tid][1]);
        g_stats[(size_t)bh * L_SZ + m0 + tid] = make_float2(M, 1.0f / Z);
    }
}

// ============================================================================
// Fused attention: per (bh, 128-row Q block), loop over 16 K/V tiles of 128:
//   S = Q K^T * 0.125; P = exp(S - M) * invZ (stats precomputed);
//   write fp32 P to attn (streaming store, never re-read);
//   store tf32 P to smem; ctx += P @ V from smem.
// Q resident in smem all kernel. K double-buffered; V prefetched via regs.
// S phase: warps 4m x 4n tile 32x32. AV phase: warps 4m x 4n tile 32x16(dh).
// ctx per warp = disjoint (32m x 16dh) accumulated over all tiles.
// smem = 208896 B -> 1 CTA/SM, 16 warps.
// ============================================================================
static constexpr int ATTN_SMEM = (128 * 68 + 2 * 128 * 68 + 128 * 72 + 128 * 132) * 4; // 208896

__global__ void __launch_bounds__(512) attn_kernel(float* __restrict__ out, int fb)
{
    extern __shared__ unsigned sh[];
    unsigned (*Qs)[68]       = (unsigned(*)[68])sh;                         // 8704
    unsigned (*Ks)[128][68]  = (unsigned(*)[128][68])(sh + 8704);           // 17408
    unsigned (*Vs)[72]       = (unsigned(*)[72])(sh + 26112);               // 9216
    unsigned (*Ps)[132]      = (unsigned(*)[132])(sh + 35328);              // 16896

    float* attn = fb ? g_attn_fb : out + OUT_ELEMS;
    const int bh = blockIdx.y;
    const int m0 = blockIdx.x * 128;
    const int b  = bh >> 4;
    const int h  = bh & 15;

    const int tid  = threadIdx.x;
    const int lane = tid & 31;
    const int wid  = tid >> 5;
    const int g = lane >> 2, t = lane & 3;
    const int warp_m = wid & 3, warp_n = wid >> 2;

    const float* Qb = g_q + (size_t)bh * L_SZ * DH_SZ;
    const float* Kb = g_k + (size_t)bh * L_SZ * DH_SZ;
    const float* Vb = g_v + (size_t)bh * L_SZ * DH_SZ;
    float* Sb = attn + (size_t)bh * L_SZ * L_SZ;

    const int lr = tid >> 4;          // 0..31 (+32*i), 16 float4 per 64-wide row
    const int lc = (tid & 15) << 2;

    // per-thread softmax stats for the 4 rows this thread's fragments touch
    float rowM[2][2], rowI[2][2];
#pragma unroll
    for (int i = 0; i < 2; i++) {
        int rl = warp_m * 32 + i * 16 + g;
        float2 s0 = g_stats[(size_t)bh * L_SZ + m0 + rl];
        float2 s1 = g_stats[(size_t)bh * L_SZ + m0 + rl + 8];
        rowM[i][0] = s0.x; rowI[i][0] = s0.y;
        rowM[i][1] = s1.x; rowI[i][1] = s1.y;
    }

    // ctx accumulators: warp tile 32(m) x 16(dh)
    float ctx[2][2][4];
#pragma unroll
    for (int i = 0; i < 2; i++)
#pragma unroll
        for (int j = 0; j < 2; j++)
#pragma unroll
            for (int c = 0; c < 4; c++) ctx[i][j][c] = 0.f;

    // preload Q (resident), K tile 0, V tile 0
#pragma unroll
    for (int i = 0; i < 4; i++) {
        int r = lr + i * 32;
        float4 fq = *(const float4*)(Qb + (size_t)(m0 + r) * DH_SZ + lc);
        *(uint4*)&Qs[r][lc] = make_uint4(f2tf(fq.x), f2tf(fq.y), f2tf(fq.z), f2tf(fq.w));
        float4 fk = *(const float4*)(Kb + (size_t)r * DH_SZ + lc);
        *(uint4*)&Ks[0][r][lc] = make_uint4(f2tf(fk.x), f2tf(fk.y), f2tf(fk.z), f2tf(fk.w));
        float4 fv = *(const float4*)(Vb + (size_t)r * DH_SZ + lc);
        *(uint4*)&Vs[r][lc] = make_uint4(f2tf(fv.x), f2tf(fv.y), f2tf(fv.z), f2tf(fv.w));
    }
    __syncthreads();

    int st = 0;
    for (int it = 0; it < 16; it++) {
        const bool nxt = it < 15;
        // prefetch next K/V tiles into registers (hidden under S mma)
        float4 kreg[4], vreg[4];
        if (nxt) {
            const float* Kn = Kb + (size_t)(it + 1) * 128 * DH_SZ;
            const float* Vn = Vb + (size_t)(it + 1) * 128 * DH_SZ;
#pragma unroll
            for (int i = 0; i < 4; i++) {
                int r = lr + i * 32;
                kreg[i] = *(const float4*)(Kn + (size_t)r * DH_SZ + lc);
                vreg[i] = *(const float4*)(Vn + (size_t)r * DH_SZ + lc);
            }
        }

        // ---- S = Q K^T ----
        float pacc[2][4][4];
#pragma unroll
        for (int i = 0; i < 2; i++)
#pragma unroll
            for (int j = 0; j < 4; j++)
#pragma unroll
                for (int c = 0; c < 4; c++) pacc[i][j][c] = 0.f;

#pragma unroll
        for (int kk = 0; kk < 64; kk += 8) {
            unsigned af[2][4], bf[4][2];
#pragma unroll
            for (int i = 0; i < 2; i++) {
                int rb = warp_m * 32 + i * 16 + g;
                af[i][0] = Qs[rb][kk + t];
                af[i][1] = Qs[rb + 8][kk + t];
                af[i][2] = Qs[rb][kk + t + 4];
                af[i][3] = Qs[rb + 8][kk + t + 4];
            }
#pragma unroll
            for (int j = 0; j < 4; j++) {
                int cb = warp_n * 32 + j * 8 + g;
                bf[j][0] = Ks[st][cb][kk + t];
                bf[j][1] = Ks[st][cb][kk + t + 4];
            }
#pragma unroll
            for (int i = 0; i < 2; i++)
#pragma unroll
                for (int j = 0; j < 4; j++)
                    mma8(pacc[i][j], af[i], bf[j]);
        }

        // park next K into the other smem stage (double-buffered)
        if (nxt) {
#pragma unroll
            for (int i = 0; i < 4; i++) {
                int r = lr + i * 32;
                *(uint4*)&Ks[st ^ 1][r][lc] =
                    make_uint4(f2tf(kreg[i].x), f2tf(kreg[i].y), f2tf(kreg[i].z), f2tf(kreg[i].w));
            }
        }

        // ---- normalize, write attn (fp32, streaming), park tf32 P in smem ----
#pragma unroll
        for (int i = 0; i < 2; i++) {
            int rl = warp_m * 32 + i * 16 + g;
#pragma unroll
            for (int j = 0; j < 4; j++) {
                int cl = warp_n * 32 + j * 8 + 2 * t;
                float2 lo = make_float2(__expf(pacc[i][j][0] * 0.125f - rowM[i][0]) * rowI[i][0],
                                        __expf(pacc[i][j][1] * 0.125f - rowM[i][0]) * rowI[i][0]);
                float2 hi = make_float2(__expf(pacc[i][j][2] * 0.125f - rowM[i][1]) * rowI[i][1],
                                        __expf(pacc[i][j][3] * 0.125f - rowM[i][1]) * rowI[i][1]);
                __stcs((float2*)(Sb + (size_t)(m0 + rl) * L_SZ + it * 128 + cl), lo);
                __stcs((float2*)(Sb + (size_t)(m0 + rl + 8) * L_SZ + it * 128 + cl), hi);
                *(uint2*)&Ps[rl][cl]     = make_uint2(f2tf(lo.x), f2tf(lo.y));
                *(uint2*)&Ps[rl + 8][cl] = make_uint2(f2tf(hi.x), f2tf(hi.y));
            }
        }
        __syncthreads();   // Ps complete; Ks[st] fully consumed

        // ---- ctx += P @ V (from smem) ----
#pragma unroll
        for (int kk = 0; kk < 128; kk += 8) {
            unsigned af[2][4], bf[2][2];
#pragma unroll
            for (int i = 0; i < 2; i++) {
                int rb = warp_m * 32 + i * 16 + g;
                af[i][0] = Ps[rb][kk + t];
                af[i][1] = Ps[rb + 8][kk + t];
                af[i][2] = Ps[rb][kk + t + 4];
                af[i][3] = Ps[rb + 8][kk + t + 4];
            }
#pragma unroll
            for (int j = 0; j < 2; j++) {
                int cb = warp_n * 16 + j * 8 + g;
                bf[j][0] = Vs[kk + t][cb];
                bf[j][1] = Vs[kk + t + 4][cb];
            }
#pragma unroll
            for (int i = 0; i < 2; i++)
#pragma unroll
                for (int j = 0; j < 2; j++)
                    mma8(ctx[i][j], af[i], bf[j]);
        }
        __syncthreads();   // AV done -> Vs, Ps free

        // park next V (visible to all after next barrier, before next AV)
        if (nxt) {
#pragma unroll
            for (int i = 0; i < 4; i++) {
                int r = lr + i * 32;
                *(uint4*)&Vs[r][lc] =
                    make_uint4(f2tf(vreg[i].x), f2tf(vreg[i].y), f2tf(vreg[i].z), f2tf(vreg[i].w));
            }
        }
        st ^= 1;
    }

    // ---- write ctx in concat layout (B, L, D) ----
#pragma unroll
    for (int i = 0; i < 2; i++) {
#pragma unroll
        for (int j = 0; j < 2; j++) {
            int l = m0 + warp_m * 32 + i * 16 + g;
            int c = warp_n * 16 + j * 8 + 2 * t;
            float* d0 = g_ctx + ((size_t)b * L_SZ + l) * D_SZ + h * DH_SZ + c;
            float* d1 = g_ctx + ((size_t)b * L_SZ + l + 8) * D_SZ + h * DH_SZ + c;
            *(float2*)d0 = make_float2(ctx[i][j][0], ctx[i][j][1]);
            *(float2*)d1 = make_float2(ctx[i][j][2], ctx[i][j][3]);
        }
    }
}

// ============================================================================
extern "C" void kernel_launch(void* const* d_in, const int* in_sizes, int n_in,
                              void* d_out, int out_size)
{
    (void)in_sizes; (void)n_in;
    const float* x  = (const float*)d_in[0];
    const float* Wq = (const float*)d_in[1];
    const float* Wk = (const float*)d_in[2];
    const float* Wv = (const float*)d_in[3];
    const float* Wo = (const float*)d_in[4];
    float* out = (float*)d_out;

    const int fb = ((size_t)out_size < OUT_ELEMS + ATTN_ELEMS) ? 1 : 0;

    cudaFuncSetAttribute(proj_kernel,  cudaFuncAttributeMaxDynamicSharedMemorySize, PROJ_SMEM);
    cudaFuncSetAttribute(stats_kernel, cudaFuncAttributeMaxDynamicSharedMemorySize, STAT_SMEM);
    cudaFuncSetAttribute(attn_kernel,  cudaFuncAttributeMaxDynamicSharedMemorySize, ATTN_SMEM);

    // 1. fused QKV projections (grid.z selects Wq/Wk/Wv)
    proj_kernel<<<dim3(8, 32, 3), 512, PROJ_SMEM>>>(x, Wq, Wk, Wv, nullptr, -1);
    // 2. per-row softmax stats (M, 1/Z) via QK^T recompute
    stats_kernel<<<dim3(16, 32), 512, STAT_SMEM>>>();
    // 3. fused scores + normalize + attn-write + AV (ctx into g_ctx)
    attn_kernel<<<dim3(16, 32), 512, ATTN_SMEM>>>(out, fb);
    // 4. out-projection
    proj_kernel<<<dim3(8, 32, 1), 512, PROJ_SMEM>>>(nullptr, Wo, nullptr, nullptr, out, 3);
}